// round 12
// baseline (speedup 1.0000x reference)
#include <cuda_runtime.h>
#include <cstdint>

#define Fdim 16
#define Sdim 512
#define Odim 32
#define Bdim 256
#define NCH  32            // shift chunks
#define SC   16            // shifts per chunk
#define BT   64            // batch rows per btile
#define NBT  4             // Bdim / BT
#define SF   (Sdim * Fdim) // floats per batch row
#define XSTR 257           // padded xs row stride (odd -> conflict-free lane reads)

// Partial maxima: [ch][b][f][o/4] float4 = 16.8 MB (L2-resident)
__device__ float4 g_partial[NCH * Bdim * Fdim * (Odim / 4)];

// ---------------------------------------------------------------------------
// Kernel 1: lanes = batch rows. Thread owns (b=lane, b+32) x (warp's f) x 32 o.
// x: conflict-free scalar LDS (unique data per lane). W: broadcast LDS.128.
// ---------------------------------------------------------------------------
__global__ __launch_bounds__(256) void k1_partial(const float* __restrict__ x,
                                                  const float* __restrict__ W) {
    extern __shared__ float sm[];
    float* xs = sm;               // [BT][XSTR] = 64*257 floats (~65.8 KB)
    float* ws = sm + BT * XSTR;   // [SC][Fdim][Odim] = 8192 floats (32 KB)

    const int tid   = threadIdx.x;
    const int btile = blockIdx.x;   // 0..3
    const int ch    = blockIdx.y;   // 0..31

    // ---- stage x: 64 rows x 256 floats. float4 LDG + 4 scalar STS
    //      (scalar stores: alignment-safe with odd XSTR) ----
    #pragma unroll
    for (int it = 0; it < 16; ++it) {
        int idx = it * 256 + tid;          // 0..4095 float4s
        int b   = idx >> 6;                // 64 float4 per row
        int q   = idx & 63;
        float4 v = *(const float4*)(x + (size_t)(btile * BT + b) * SF
                                      + ch * (SC * Fdim) + q * 4);
        float* dst = xs + b * XSTR + q * 4;
        dst[0] = v.x; dst[1] = v.y; dst[2] = v.z; dst[3] = v.w;
    }

    // ---- stage W chunk (8192 floats, contiguous, coalesced, aligned) ----
    {
        const float4* wsrc = (const float4*)(W + (size_t)ch * SC * Fdim * Odim);
        #pragma unroll
        for (int it = 0; it < 8; ++it)
            ((float4*)ws)[it * 256 + tid] = wsrc[it * 256 + tid];
    }
    __syncthreads();

    const int l = tid & 31;        // lane -> batch row
    const int w = tid >> 5;        // warp 0..7 -> f pair {2w, 2w+1}

    const float NEG = __int_as_float(0xff800000);   // -inf

    #pragma unroll
    for (int fi = 0; fi < 2; ++fi) {
        const int f = w * 2 + fi;

        float4 aLo[8], aHi[8];
        #pragma unroll
        for (int k = 0; k < 8; ++k) {
            aLo[k] = make_float4(NEG, NEG, NEG, NEG);
            aHi[k] = make_float4(NEG, NEG, NEG, NEG);
        }

        #pragma unroll 4
        for (int s = 0; s < SC; ++s) {
            // x: conflict-free scalar LDS (bank = (l + const) mod 32, distinct)
            const float xlo = xs[l * XSTR + s * Fdim + f];
            const float xhi = xs[(l + 32) * XSTR + s * Fdim + f];
            const float4* wr = (const float4*)(ws + (s * Fdim + f) * Odim);
            #pragma unroll
            for (int k = 0; k < 8; ++k) {
                const float4 wv = wr[k];   // warp-uniform broadcast LDS.128
                aLo[k].x = fmaxf(aLo[k].x, wv.x * xlo);
                aLo[k].y = fmaxf(aLo[k].y, wv.y * xlo);
                aLo[k].z = fmaxf(aLo[k].z, wv.z * xlo);
                aLo[k].w = fmaxf(aLo[k].w, wv.w * xlo);
                aHi[k].x = fmaxf(aHi[k].x, wv.x * xhi);
                aHi[k].y = fmaxf(aHi[k].y, wv.y * xhi);
                aHi[k].z = fmaxf(aHi[k].z, wv.z * xhi);
                aHi[k].w = fmaxf(aHi[k].w, wv.w * xhi);
            }
        }

        // ---- store partials: [ch][b][f][o/4] (16-B aligned float4) ----
        const int bLo = btile * BT + l;
        const int bHi = bLo + 32;
        float4* pLo = g_partial + ((size_t)(ch * Bdim + bLo) * Fdim + f) * 8;
        float4* pHi = g_partial + ((size_t)(ch * Bdim + bHi) * Fdim + f) * 8;
        #pragma unroll
        for (int k = 0; k < 8; ++k) {
            pLo[k] = aLo[k];
            pHi[k] = aHi[k];
        }
    }
}

// ---------------------------------------------------------------------------
// Kernel 2: out[b,o] = relu( bias[o] + sum_f max_ch partial )
// 256 blocks x 128 threads; thread = float4 #t of the 512-float (f,o) slab.
// ---------------------------------------------------------------------------
__global__ __launch_bounds__(128) void k2_reduce(const float* __restrict__ bias,
                                                 float* __restrict__ out) {
    const int b = blockIdx.x;
    const int t = threadIdx.x;

    const float NEG = __int_as_float(0xff800000);
    float4 m = make_float4(NEG, NEG, NEG, NEG);

    #pragma unroll
    for (int c = 0; c < NCH; ++c) {
        float4 v = __ldcg(&g_partial[(size_t)(c * Bdim + b) * 128 + t]);
        m.x = fmaxf(m.x, v.x); m.y = fmaxf(m.y, v.y);
        m.z = fmaxf(m.z, v.z); m.w = fmaxf(m.w, v.w);
    }

    // float4 #t covers (f = t>>3, o = 4*(t&7))
    const int f  = t >> 3;
    const int o4 = (t & 7) * 4;
    __shared__ float red[Fdim][Odim + 1];
    red[f][o4 + 0] = m.x;
    red[f][o4 + 1] = m.y;
    red[f][o4 + 2] = m.z;
    red[f][o4 + 3] = m.w;
    __syncthreads();

    if (t < Odim) {
        float sum = bias[t];
        #pragma unroll
        for (int ff = 0; ff < Fdim; ++ff) sum += red[ff][t];
        out[b * Odim + t] = fmaxf(sum, 0.0f);
    }
}

// ---------------------------------------------------------------------------
extern "C" void kernel_launch(void* const* d_in, const int* in_sizes, int n_in,
                              void* d_out, int out_size) {
    const float* x    = (const float*)d_in[0];   // [256, 8192]
    const float* W    = (const float*)d_in[1];   // [8192, 32]
    const float* bias = (const float*)d_in[2];   // [32]
    float* out        = (float*)d_out;           // [256, 32]

    cudaFuncSetAttribute(k1_partial, cudaFuncAttributeMaxDynamicSharedMemorySize,
                         100 * 1024);

    dim3 g1(NBT, NCH);
    k1_partial<<<g1, 256, (BT * XSTR + SC * Fdim * Odim) * sizeof(float)>>>(x, W);
    k2_reduce<<<Bdim, 128>>>(bias, out);
}